// round 2
// baseline (speedup 1.0000x reference)
#include <cuda_runtime.h>
#include <cuda_bf16.h>
#include <math.h>

// Problem constants (from reference): NATOMS=50000, ND=64, H1=128, H2=64
#define MAX_ATOMS 50000
#define ND 64
#define H1 128
#define H2 64

// Scratch for dEdD (gradient of sum(mlp) wrt x): 50000 x 64 fp32 = 12.8 MB
__device__ float g_dEdD[MAX_ATOMS * ND];

// ---------------------------------------------------------------------------
// MLP forward + backward kernel.
// Block: 256 threads = 8 groups of 32 lanes. Each group handles 8 atoms per
// iteration (64 atoms/block/iter). Weights live in shared memory in BOTH
// forward and transposed layouts so every matvec reads conflict-free float4.
// Per-lane register tile: 4 output columns x up to 8 atoms.
// ---------------------------------------------------------------------------
__global__ void __launch_bounds__(256, 1)
mlp_kernel(const float* __restrict__ x, const int* __restrict__ indices,
           const float* __restrict__ W1, const float* __restrict__ b1,
           const float* __restrict__ W2, const float* __restrict__ b2,
           const float* __restrict__ W3, const float* __restrict__ b3,
           float* __restrict__ energy, int natoms)
{
    extern __shared__ float sm[];
    float* W1f = sm;                 // [64][128]  : W1f[k*128+j] = W1[k][j]
    float* W1t = W1f + 64 * 128;     // [128][64]  : W1t[t*64+d]  = W1[d][t]
    float* W2f = W1t + 128 * 64;     // [128][64]  : W2f[k*64+j]  = W2[k][j]
    float* W2t = W2f + 128 * 64;     // [64][128]  : W2t[k*128+t] = W2[t][k]
    float* xs  = W2t + 64 * 128;     // [64 atoms][64]
    float* h1s = xs  + 64 * 64;      // [64 atoms][128]   (reused for g1)
    float* h2s = h1s + 64 * 128;     // [64 atoms][64]    (reused for d2)
    float* b1s = h2s + 64 * 64;      // [128]
    float* b2s = b1s + 128;          // [64]
    float* W3s = b2s + 64;           // [64]

    const int tid = threadIdx.x;

    // ---- load weights (once per block) ----
    for (int i = tid; i < 64 * 128; i += 256) {
        float v = W1[i];
        W1f[i] = v;
        W1t[(i & 127) * 64 + (i >> 7)] = v;   // transpose
    }
    for (int i = tid; i < 128 * 64; i += 256) {
        float v = W2[i];
        W2f[i] = v;
        W2t[(i & 63) * 128 + (i >> 6)] = v;   // transpose
    }
    if (tid < 128) b1s[tid] = b1[tid];
    if (tid < 64)  { b2s[tid] = b2[tid]; W3s[tid] = W3[tid]; }
    const float b3v = b3[0];
    __syncthreads();

    const int g    = tid >> 5;           // group 0..7
    const int lane = tid & 31;
    const int jv   = lane * 4;           // 0..124  (covers 128 outputs)
    const int jv2  = (lane & 15) * 4;    // 0..60   (covers 64 outputs)
    const int sub  = lane >> 4;          // 0/1 : which 4-atom half

    for (int base = blockIdx.x * 64; base < natoms; base += gridDim.x * 64) {
        // ---- load x tile: 64 atoms x 64 ----
        for (int i = tid; i < 64 * 64; i += 256) {
            int atom = base + (i >> 6);
            xs[i] = (atom < natoms) ? x[(size_t)atom * 64 + (i & 63)] : 0.f;
        }
        __syncthreads();

        // ---- layer 1: h1 = tanh(x @ W1 + b1), group's 8 atoms ----
        {
            float4 acc[8];
            float4 bini = *(const float4*)(b1s + jv);
            #pragma unroll
            for (int a = 0; a < 8; a++) acc[a] = bini;
            const float* xg = xs + g * 8 * 64;
            #pragma unroll 4
            for (int k = 0; k < 64; k++) {
                float4 w = *(const float4*)(W1f + k * 128 + jv);
                #pragma unroll
                for (int a = 0; a < 8; a++) {
                    float xv = xg[a * 64 + k];
                    acc[a].x += w.x * xv; acc[a].y += w.y * xv;
                    acc[a].z += w.z * xv; acc[a].w += w.w * xv;
                }
            }
            #pragma unroll
            for (int a = 0; a < 8; a++) {
                float4 h;
                h.x = tanhf(acc[a].x); h.y = tanhf(acc[a].y);
                h.z = tanhf(acc[a].z); h.w = tanhf(acc[a].w);
                *(float4*)(h1s + (g * 8 + a) * 128 + jv) = h;
            }
        }
        __syncthreads();

        // ---- layer 2: h2 = tanh(h1 @ W2 + b2), 4 atoms per thread-half ----
        {
            float4 acc[4];
            float4 bini = *(const float4*)(b2s + jv2);
            #pragma unroll
            for (int a = 0; a < 4; a++) acc[a] = bini;
            const float* hg = h1s + (g * 8 + sub * 4) * 128;
            #pragma unroll 4
            for (int k = 0; k < 128; k++) {
                float4 w = *(const float4*)(W2f + k * 64 + jv2);
                #pragma unroll
                for (int a = 0; a < 4; a++) {
                    float hv = hg[a * 128 + k];
                    acc[a].x += w.x * hv; acc[a].y += w.y * hv;
                    acc[a].z += w.z * hv; acc[a].w += w.w * hv;
                }
            }
            #pragma unroll
            for (int a = 0; a < 4; a++) {
                float4 h;
                h.x = tanhf(acc[a].x); h.y = tanhf(acc[a].y);
                h.z = tanhf(acc[a].z); h.w = tanhf(acc[a].w);
                *(float4*)(h2s + (g * 8 + sub * 4 + a) * 64 + jv2) = h;
            }
        }
        __syncthreads();

        // ---- energy (h2 @ W3 + b3, atomic into structure bins) and
        //      d2 = W3 * (1 - h2^2) written in-place over h2s ----
        {
            #pragma unroll
            for (int a = 0; a < 8; a++) {
                int atom = base + g * 8 + a;
                float* h2a = h2s + (g * 8 + a) * 64;
                float v0 = h2a[lane], v1 = h2a[lane + 32];
                float w0 = W3s[lane], w1 = W3s[lane + 32];
                float e = v0 * w0 + v1 * w1;
                h2a[lane]      = w0 * (1.f - v0 * v0);
                h2a[lane + 32] = w1 * (1.f - v1 * v1);
                #pragma unroll
                for (int off = 16; off; off >>= 1)
                    e += __shfl_down_sync(0xffffffffu, e, off);
                if (lane == 0 && atom < natoms)
                    atomicAdd(&energy[indices[atom]], e + b3v);
            }
        }
        __syncthreads();

        // ---- g1 = (1 - h1^2) * (W2 @ d2), in-place over h1s ----
        {
            float4 acc[8];
            #pragma unroll
            for (int a = 0; a < 8; a++) acc[a] = make_float4(0.f, 0.f, 0.f, 0.f);
            const float* d2g = h2s + g * 8 * 64;
            #pragma unroll 4
            for (int k = 0; k < 64; k++) {
                float4 w = *(const float4*)(W2t + k * 128 + jv);
                #pragma unroll
                for (int a = 0; a < 8; a++) {
                    float dv = d2g[a * 64 + k];
                    acc[a].x += w.x * dv; acc[a].y += w.y * dv;
                    acc[a].z += w.z * dv; acc[a].w += w.w * dv;
                }
            }
            #pragma unroll
            for (int a = 0; a < 8; a++) {
                float* h1a = h1s + (g * 8 + a) * 128 + jv;
                float4 h = *(const float4*)h1a;
                float4 r;
                r.x = acc[a].x * (1.f - h.x * h.x);
                r.y = acc[a].y * (1.f - h.y * h.y);
                r.z = acc[a].z * (1.f - h.z * h.z);
                r.w = acc[a].w * (1.f - h.w * h.w);
                *(float4*)h1a = r;
            }
        }
        __syncthreads();

        // ---- dEdD = W1 @ g1, write to global scratch ----
        {
            float4 acc[4];
            #pragma unroll
            for (int a = 0; a < 4; a++) acc[a] = make_float4(0.f, 0.f, 0.f, 0.f);
            const float* gg = h1s + (g * 8 + sub * 4) * 128;
            #pragma unroll 4
            for (int t = 0; t < 128; t++) {
                float4 w = *(const float4*)(W1t + t * 64 + jv2);
                #pragma unroll
                for (int a = 0; a < 4; a++) {
                    float gv = gg[a * 128 + t];
                    acc[a].x += w.x * gv; acc[a].y += w.y * gv;
                    acc[a].z += w.z * gv; acc[a].w += w.w * gv;
                }
            }
            #pragma unroll
            for (int a = 0; a < 4; a++) {
                int atom = base + g * 8 + sub * 4 + a;
                if (atom < natoms)
                    *(float4*)(g_dEdD + (size_t)atom * 64 + jv2) = acc[a];
            }
        }
        __syncthreads();
    }
}

// ---------------------------------------------------------------------------
// Forces kernel: one warp per pair p.
//   neigh = xd_indx[3p][0];  g = dEdD[neigh]
//   s_c = dot(xd[3p+c], g)   for c in {0,1,2}
//   forces[uj[3p+c]*3 + c] -= s_c    (atomic)
// Streams 768 MB of xd -> HBM-bound.
// ---------------------------------------------------------------------------
__global__ void __launch_bounds__(256)
forces_kernel(const float* __restrict__ xd, const int* __restrict__ xd_indx,
              const int* __restrict__ uj, float* __restrict__ forces, int npairs)
{
    int p = (blockIdx.x * blockDim.x + threadIdx.x) >> 5;
    int lane = threadIdx.x & 31;
    if (p >= npairs) return;

    int neigh = xd_indx[6 * p];   // row 3p, col 0
    const float2* gp = (const float2*)(g_dEdD + (size_t)neigh * 64);
    float2 gv = gp[lane];

    const float2* r0 = (const float2*)(xd + (size_t)3 * p * 64);
    float2 a0 = r0[lane];
    float2 a1 = r0[lane + 32];
    float2 a2 = r0[lane + 64];

    float s0 = a0.x * gv.x + a0.y * gv.y;
    float s1 = a1.x * gv.x + a1.y * gv.y;
    float s2 = a2.x * gv.x + a2.y * gv.y;

    #pragma unroll
    for (int off = 16; off; off >>= 1) {
        s0 += __shfl_down_sync(0xffffffffu, s0, off);
        s1 += __shfl_down_sync(0xffffffffu, s1, off);
        s2 += __shfl_down_sync(0xffffffffu, s2, off);
    }
    if (lane == 0) {
        int j0 = uj[3 * p], j1 = uj[3 * p + 1], j2 = uj[3 * p + 2];
        atomicAdd(&forces[3 * j0 + 0], -s0);
        atomicAdd(&forces[3 * j1 + 1], -s1);
        atomicAdd(&forces[3 * j2 + 2], -s2);
    }
}

// ---------------------------------------------------------------------------
extern "C" void kernel_launch(void* const* d_in, const int* in_sizes, int n_in,
                              void* d_out, int out_size)
{
    const float* x        = (const float*)d_in[0];
    const float* xd       = (const float*)d_in[1];
    const int*   indices  = (const int*)  d_in[2];
    // d_in[3] = atoms_per_structure (only its length matters)
    const int*   xd_indx  = (const int*)  d_in[4];
    const int*   uj       = (const int*)  d_in[5];
    const float* W1       = (const float*)d_in[6];
    const float* b1       = (const float*)d_in[7];
    const float* W2       = (const float*)d_in[8];
    const float* b2       = (const float*)d_in[9];
    const float* W3       = (const float*)d_in[10];
    const float* b3       = (const float*)d_in[11];
    float* out = (float*)d_out;

    int natoms  = in_sizes[0] / ND;       // 50000
    int nstruct = in_sizes[3];            // 250
    int npairs  = in_sizes[5] / 3;        // 1000000

    // zero energy + forces region (d_out is poisoned)
    cudaMemsetAsync(out, 0, (size_t)out_size * sizeof(float), 0);

    // MLP fwd+bwd
    const int smem_bytes = (64*128 + 128*64 + 128*64 + 64*128   // weights x2 layouts
                            + 64*64 + 64*128 + 64*64            // xs,h1s,h2s
                            + 128 + 64 + 64) * (int)sizeof(float);
    cudaFuncSetAttribute(mlp_kernel, cudaFuncAttributeMaxDynamicSharedMemorySize,
                         smem_bytes);
    mlp_kernel<<<148, 256, smem_bytes>>>(x, indices, W1, b1, W2, b2, W3, b3,
                                         out, natoms);

    // forces
    int warps = npairs;
    int blocks = (warps * 32 + 255) / 256;
    forces_kernel<<<blocks, 256>>>(xd, xd_indx, uj, out + nstruct, npairs);
}

// round 3
// speedup vs baseline: 1.6930x; 1.6930x over previous
#include <cuda_runtime.h>
#include <cuda_bf16.h>
#include <math.h>

#define MAX_ATOMS 50000
#define ND 64

// Scratch for dEdD: 50000 x 64 fp32 = 12.8 MB (stays L2-resident for forces)
__device__ float g_dEdD[MAX_ATOMS * ND];

typedef unsigned long long u64;

// Packed fp32x2 FMA (sm_103a FFMA2) — 2x FLOP per instruction
__device__ __forceinline__ void fma2(u64 &d, u64 a, u64 b) {
    asm("fma.rn.f32x2 %0, %1, %2, %0;" : "+l"(d) : "l"(a), "l"(b));
}
__device__ __forceinline__ float2 unpk(u64 v) {
    float2 r; asm("mov.b64 {%0, %1}, %2;" : "=f"(r.x), "=f"(r.y) : "l"(v));
    return r;
}

// ---------------------------------------------------------------------------
// MLP forward + backward. 256 threads = 8 warps; 32 atoms per tile iteration,
// 4 atoms per warp. Weights in smem in forward + transposed layouts.
// Activations stored DUPLICATED ({v,v} float2) so the broadcast operand of
// every fma.f32x2 is a single conflict-free LDS.64.
// Output-j mapping per lane: {2*lane, 2*lane+1} and {+64 block} -> all
// weight LDS.64 at 8B/lane stride and all act stores at 16B/lane stride:
// conflict-free.
// ---------------------------------------------------------------------------
__global__ void __launch_bounds__(256, 1)
mlp_kernel(const float* __restrict__ x, const int* __restrict__ indices,
           const float* __restrict__ W1, const float* __restrict__ b1,
           const float* __restrict__ W2, const float* __restrict__ b2,
           const float* __restrict__ W3, const float* __restrict__ b3,
           float* __restrict__ energy, int natoms)
{
    extern __shared__ float sm[];
    float*  W1f  = sm;                       // [64][128]
    float*  W1t  = W1f + 8192;               // [128][64]
    float*  W2f  = W1t + 8192;               // [128][64]
    float*  W2t  = W2f + 8192;               // [64][128]
    float2* xs2  = (float2*)(W2t + 8192);    // [32 atoms][64]  dup
    float2* h1s2 = xs2 + 32 * 64;            // [32][128] dup (reused for g1)
    float2* h2s2 = h1s2 + 32 * 128;          // [32][64]  dup (reused for d2)
    float*  b1s  = (float*)(h2s2 + 32 * 64); // 128
    float*  b2s  = b1s + 128;                // 64
    float*  W3s  = b2s + 64;                 // 64

    const int tid = threadIdx.x;

    for (int i = tid; i < 8192; i += 256) {
        float v = W1[i];
        W1f[i] = v;
        W1t[(i & 127) * 64 + (i >> 7)] = v;
    }
    for (int i = tid; i < 8192; i += 256) {
        float v = W2[i];
        W2f[i] = v;
        W2t[(i & 63) * 128 + (i >> 6)] = v;
    }
    if (tid < 128) b1s[tid] = b1[tid];
    if (tid < 64)  { b2s[tid] = b2[tid]; W3s[tid] = W3[tid]; }
    const float b3v = b3[0];
    __syncthreads();

    const int g    = tid >> 5;     // warp 0..7
    const int lane = tid & 31;
    const int li   = lane & 15;
    const int sub  = lane >> 4;

    for (int base = blockIdx.x * 32; base < natoms; base += gridDim.x * 32) {
        // ---- x tile, duplicated ----
        for (int i = tid; i < 2048; i += 256) {
            int atom = base + (i >> 6);
            float v = (atom < natoms) ? x[(size_t)atom * 64 + (i & 63)] : 0.f;
            xs2[i] = make_float2(v, v);
        }
        __syncthreads();

        // ---- L1: h1 = tanh(x @ W1 + b1); 4 atoms/warp, 4 outputs/lane ----
        {
            u64 acc0[4], acc1[4];
            u64 bi0 = *(const u64*)(b1s + 2 * lane);
            u64 bi1 = *(const u64*)(b1s + 64 + 2 * lane);
            #pragma unroll
            for (int a = 0; a < 4; a++) { acc0[a] = bi0; acc1[a] = bi1; }
            const float2* xg = xs2 + (g * 4) * 64;
            #pragma unroll 4
            for (int k = 0; k < 64; k++) {
                u64 w0 = *(const u64*)(W1f + k * 128 + 2 * lane);
                u64 w1 = *(const u64*)(W1f + k * 128 + 64 + 2 * lane);
                #pragma unroll
                for (int a = 0; a < 4; a++) {
                    u64 xv = *(const u64*)(xg + a * 64 + k);
                    fma2(acc0[a], w0, xv);
                    fma2(acc1[a], w1, xv);
                }
            }
            #pragma unroll
            for (int a = 0; a < 4; a++) {
                float2 p0 = unpk(acc0[a]), p1 = unpk(acc1[a]);
                float t0 = tanhf(p0.x), t1 = tanhf(p0.y);
                float t2 = tanhf(p1.x), t3 = tanhf(p1.y);
                *(float4*)(h1s2 + (g * 4 + a) * 128 + 2 * lane)
                    = make_float4(t0, t0, t1, t1);
                *(float4*)(h1s2 + (g * 4 + a) * 128 + 64 + 2 * lane)
                    = make_float4(t2, t2, t3, t3);
            }
        }
        __syncthreads();

        // ---- L2: h2 = tanh(h1 @ W2 + b2); 2 atoms per half-warp ----
        {
            u64 acc0[2], acc1[2];
            u64 bi0 = *(const u64*)(b2s + 2 * li);
            u64 bi1 = *(const u64*)(b2s + 32 + 2 * li);
            #pragma unroll
            for (int a = 0; a < 2; a++) { acc0[a] = bi0; acc1[a] = bi1; }
            const float2* hg = h1s2 + (g * 4 + sub * 2) * 128;
            #pragma unroll 4
            for (int k = 0; k < 128; k++) {
                u64 w0 = *(const u64*)(W2f + k * 64 + 2 * li);
                u64 w1 = *(const u64*)(W2f + k * 64 + 32 + 2 * li);
                #pragma unroll
                for (int a = 0; a < 2; a++) {
                    u64 hv = *(const u64*)(hg + a * 128 + k);
                    fma2(acc0[a], w0, hv);
                    fma2(acc1[a], w1, hv);
                }
            }
            #pragma unroll
            for (int a = 0; a < 2; a++) {
                float2 p0 = unpk(acc0[a]), p1 = unpk(acc1[a]);
                float t0 = tanhf(p0.x), t1 = tanhf(p0.y);
                float t2 = tanhf(p1.x), t3 = tanhf(p1.y);
                int atom_l = g * 4 + sub * 2 + a;
                *(float4*)(h2s2 + atom_l * 64 + 2 * li)
                    = make_float4(t0, t0, t1, t1);
                *(float4*)(h2s2 + atom_l * 64 + 32 + 2 * li)
                    = make_float4(t2, t2, t3, t3);
            }
        }
        __syncthreads();

        // ---- energy atomics + d2 = W3 * (1 - h2^2) in-place ----
        {
            #pragma unroll
            for (int a = 0; a < 4; a++) {
                int atom = base + g * 4 + a;
                float2* h2a = h2s2 + (g * 4 + a) * 64;
                float v0 = h2a[lane].x, v1 = h2a[lane + 32].x;
                float w0 = W3s[lane],   w1 = W3s[lane + 32];
                float e = v0 * w0 + v1 * w1;
                float d0 = w0 * (1.f - v0 * v0);
                float d1 = w1 * (1.f - v1 * v1);
                h2a[lane]      = make_float2(d0, d0);
                h2a[lane + 32] = make_float2(d1, d1);
                #pragma unroll
                for (int off = 16; off; off >>= 1)
                    e += __shfl_down_sync(0xffffffffu, e, off);
                if (lane == 0 && atom < natoms)
                    atomicAdd(&energy[indices[atom]], e + b3v);
            }
        }
        __syncthreads();

        // ---- bwd1: g1 = (1 - h1^2) * (W2t @ d2), in-place over h1s2 ----
        {
            u64 acc0[4] = {0, 0, 0, 0}, acc1[4] = {0, 0, 0, 0};
            const float2* dg = h2s2 + (g * 4) * 64;
            #pragma unroll 4
            for (int k = 0; k < 64; k++) {
                u64 w0 = *(const u64*)(W2t + k * 128 + 2 * lane);
                u64 w1 = *(const u64*)(W2t + k * 128 + 64 + 2 * lane);
                #pragma unroll
                for (int a = 0; a < 4; a++) {
                    u64 dv = *(const u64*)(dg + a * 64 + k);
                    fma2(acc0[a], w0, dv);
                    fma2(acc1[a], w1, dv);
                }
            }
            #pragma unroll
            for (int a = 0; a < 4; a++) {
                float4* p0 = (float4*)(h1s2 + (g * 4 + a) * 128 + 2 * lane);
                float4* p1 = (float4*)(h1s2 + (g * 4 + a) * 128 + 64 + 2 * lane);
                float4 h0 = *p0, h1v = *p1;
                float2 a0 = unpk(acc0[a]), a1 = unpk(acc1[a]);
                float g0 = a0.x * (1.f - h0.x * h0.x);
                float g1 = a0.y * (1.f - h0.z * h0.z);
                float g2 = a1.x * (1.f - h1v.x * h1v.x);
                float g3 = a1.y * (1.f - h1v.z * h1v.z);
                *p0 = make_float4(g0, g0, g1, g1);
                *p1 = make_float4(g2, g2, g3, g3);
            }
        }
        __syncthreads();

        // ---- bwd2: dEdD = W1t-matvec(g1) -> global ----
        {
            u64 acc0[2] = {0, 0}, acc1[2] = {0, 0};
            const float2* gg = h1s2 + (g * 4 + sub * 2) * 128;
            #pragma unroll 4
            for (int t = 0; t < 128; t++) {
                u64 w0 = *(const u64*)(W1t + t * 64 + 2 * li);
                u64 w1 = *(const u64*)(W1t + t * 64 + 32 + 2 * li);
                #pragma unroll
                for (int a = 0; a < 2; a++) {
                    u64 gv = *(const u64*)(gg + a * 128 + t);
                    fma2(acc0[a], w0, gv);
                    fma2(acc1[a], w1, gv);
                }
            }
            #pragma unroll
            for (int a = 0; a < 2; a++) {
                int atom = base + g * 4 + sub * 2 + a;
                if (atom < natoms) {
                    float2 r0 = unpk(acc0[a]), r1 = unpk(acc1[a]);
                    *(float2*)(g_dEdD + (size_t)atom * 64 + 2 * li)      = r0;
                    *(float2*)(g_dEdD + (size_t)atom * 64 + 32 + 2 * li) = r1;
                }
            }
        }
        __syncthreads();
    }
}

// ---------------------------------------------------------------------------
// Forces: 2 pairs per warp, one 16-lane group per pair. float4 loads,
// __ldcs on the 768MB xd stream (keep L2 for the dEdD gather table).
//   s_c = dot(xd[3p+c], dEdD[xd_indx[3p][0]]);  forces[3*uj[3p+c]+c] -= s_c
// ---------------------------------------------------------------------------
__global__ void __launch_bounds__(256)
forces_kernel(const float* __restrict__ xd, const int* __restrict__ xd_indx,
              const int* __restrict__ uj, float* __restrict__ forces, int npairs)
{
    int w    = (blockIdx.x * blockDim.x + threadIdx.x) >> 5;
    int lane = threadIdx.x & 31;
    int li   = lane & 15;
    int pr   = lane >> 4;
    int p    = 2 * w + pr;
    if (2 * w >= npairs) return;
    bool valid = (p < npairs);
    int pc = valid ? p : (npairs - 1);

    int neigh = __ldg(xd_indx + 6 * pc);   // row 3p, col 0
    float4 gv = *(const float4*)(g_dEdD + (size_t)neigh * 64 + li * 4);

    const float4* xr = (const float4*)(xd + (size_t)pc * 192);
    float4 a0 = __ldcs(xr + li);
    float4 a1 = __ldcs(xr + 16 + li);
    float4 a2 = __ldcs(xr + 32 + li);

    float s0 = a0.x * gv.x + a0.y * gv.y + a0.z * gv.z + a0.w * gv.w;
    float s1 = a1.x * gv.x + a1.y * gv.y + a1.z * gv.z + a1.w * gv.w;
    float s2 = a2.x * gv.x + a2.y * gv.y + a2.z * gv.z + a2.w * gv.w;

    #pragma unroll
    for (int off = 8; off; off >>= 1) {
        s0 += __shfl_xor_sync(0xffffffffu, s0, off);
        s1 += __shfl_xor_sync(0xffffffffu, s1, off);
        s2 += __shfl_xor_sync(0xffffffffu, s2, off);
    }
    if (li == 0 && valid) {
        int j0 = __ldg(uj + 3 * pc);
        int j1 = __ldg(uj + 3 * pc + 1);
        int j2 = __ldg(uj + 3 * pc + 2);
        atomicAdd(&forces[3 * j0 + 0], -s0);
        atomicAdd(&forces[3 * j1 + 1], -s1);
        atomicAdd(&forces[3 * j2 + 2], -s2);
    }
}

// ---------------------------------------------------------------------------
extern "C" void kernel_launch(void* const* d_in, const int* in_sizes, int n_in,
                              void* d_out, int out_size)
{
    const float* x       = (const float*)d_in[0];
    const float* xd      = (const float*)d_in[1];
    const int*   indices = (const int*)  d_in[2];
    const int*   xd_indx = (const int*)  d_in[4];
    const int*   uj      = (const int*)  d_in[5];
    const float* W1      = (const float*)d_in[6];
    const float* b1      = (const float*)d_in[7];
    const float* W2      = (const float*)d_in[8];
    const float* b2      = (const float*)d_in[9];
    const float* W3      = (const float*)d_in[10];
    const float* b3      = (const float*)d_in[11];
    float* out = (float*)d_out;

    int natoms  = in_sizes[0] / ND;    // 50000
    int nstruct = in_sizes[3];         // 250
    int npairs  = in_sizes[5] / 3;     // 1000000

    cudaMemsetAsync(out, 0, (size_t)out_size * sizeof(float), 0);

    const int smem_bytes =
        (8192 * 4                     // weights, 2 layouts each
         + (32 * 64 + 32 * 128 + 32 * 64) * 2   // duplicated activations
         + 128 + 64 + 64) * (int)sizeof(float);
    cudaFuncSetAttribute(mlp_kernel, cudaFuncAttributeMaxDynamicSharedMemorySize,
                         smem_bytes);
    mlp_kernel<<<148, 256, smem_bytes>>>(x, indices, W1, b1, W2, b2, W3, b3,
                                         out, natoms);

    int nwarps = (npairs + 1) / 2;
    int blocks = (nwarps + 7) / 8;     // 8 warps per 256-thread block
    forces_kernel<<<blocks, 256>>>(xd, xd_indx, uj, out + nstruct, npairs);
}

// round 6
// speedup vs baseline: 2.1575x; 1.2744x over previous
#include <cuda_runtime.h>
#include <math.h>
#include <stdint.h>

#define MAX_ATOMS 50000

__device__ float g_dEdD[MAX_ATOMS * 64];

typedef unsigned long long u64;

__device__ __forceinline__ void fma2(u64 &d, u64 a, u64 b) {
    asm("fma.rn.f32x2 %0, %1, %2, %0;" : "+l"(d) : "l"(a), "l"(b));
}
__device__ __forceinline__ float2 unpk(u64 v) {
    float2 r; asm("mov.b64 {%0, %1}, %2;" : "=f"(r.x), "=f"(r.y) : "l"(v));
    return r;
}

// ---- smem layout (float offsets) ----
// Weights in 4 layouts, rows padded to odd-ish word counts for conflict-free
// half-warp LDS.64 (stride 66 -> bank step 2; stride 130 -> bank step 2).
#define O_W1J 0                    // [j=128][k=66] : W1J[j*66+k] = W1[k][j]
#define O_W2J (O_W1J + 128*66)     // [j=64][t=130] : W2J[j*130+t] = W2[t][j]
#define O_W2F (O_W2J + 64*130)     // [t=128][j=66] : W2F[t*66+j] = W2[t][j]
#define O_W1F (O_W2F + 128*66)     // [d=64][t=130] : W1F[d*130+t] = W1[d][t]
#define O_B1  (O_W1F + 64*130)     // 128
#define O_B2  (O_B1 + 128)         // 64
#define O_W3  (O_B2 + 64)          // 64
#define O_WRP (O_W3 + 64)          // per-warp areas
// per-warp: xs [8][68] (x, then d2) + h1 [8][132] (h1, then g1)
#define WRP_FLOATS (8*68 + 8*132)  // 1600
#define SMEM_FLOATS (O_WRP + 8 * WRP_FLOATS)

// ---------------------------------------------------------------------------
// MLP fwd+bwd. 256 threads = 8 autonomous warps; each warp processes 8-atom
// chunks grid-stride. fma.f32x2 with even/odd-k split accumulators:
//   acc = {sum_{k even} w*x, sum_{k odd} w*x};  out = acc.x + acc.y
// Both operands are consecutive-k u64s: weights from [out][k]-major smem,
// activations as non-duplicated broadcast ulonglong2 loads.
// ---------------------------------------------------------------------------
__global__ void __launch_bounds__(256, 1)
mlp_kernel(const float* __restrict__ x, const int* __restrict__ indices,
           const float* __restrict__ W1, const float* __restrict__ b1,
           const float* __restrict__ W2, const float* __restrict__ b2,
           const float* __restrict__ W3, const float* __restrict__ b3,
           float* __restrict__ energy, int natoms)
{
    extern __shared__ float sm[];
    const int tid  = threadIdx.x;
    const int wid  = tid >> 5;
    const int lane = tid & 31;

    // ---- stage weights ----
    for (int i = tid; i < 64 * 128; i += 256) {   // W1 [k=64][j=128]
        int k = i >> 7, j = i & 127;
        float w = W1[i];
        sm[O_W1J + j * 66 + k]  = w;
        sm[O_W1F + k * 130 + j] = w;
    }
    for (int i = tid; i < 128 * 64; i += 256) {   // W2 [t=128][j=64]
        int t = i >> 6, j = i & 63;
        float w = W2[i];
        sm[O_W2J + j * 130 + t] = w;
        sm[O_W2F + t * 66 + j]  = w;
    }
    if (tid < 128) sm[O_B1 + tid] = b1[tid];
    if (tid < 64)  { sm[O_B2 + tid] = b2[tid]; sm[O_W3 + tid] = W3[tid]; }
    const float b3v = b3[0];
    __syncthreads();

    float* xs = sm + O_WRP + wid * WRP_FLOATS;        // [8][68]
    float* h1 = xs + 8 * 68;                           // [8][132]

    const int gwarp  = blockIdx.x * 8 + wid;
    const int nwarps = gridDim.x * 8;
    const int nchunk = (natoms + 7) >> 3;

    for (int chunk = gwarp; chunk < nchunk; chunk += nwarps) {
        const int base = chunk << 3;

        // ---- load x: 8 atoms x 64, float4 per lane ----
        #pragma unroll
        for (int q = 0; q < 4; q++) {
            int i = lane + 32 * q;            // float4 index 0..127
            int a = i >> 4, c = (i & 15) << 2;
            float4 v = make_float4(0.f, 0.f, 0.f, 0.f);
            if (base + a < natoms)
                v = *(const float4*)(x + (size_t)(base + a) * 64 + c);
            *(float4*)(xs + a * 68 + c) = v;
        }
        __syncwarp();

        // ================= L1: h1 = tanh(x @ W1 + b1) =================
        {
            u64 acc[4][8];
            #pragma unroll
            for (int jj = 0; jj < 4; jj++)
                #pragma unroll
                for (int a = 0; a < 8; a++) acc[jj][a] = 0ull;

            for (int k0 = 0; k0 < 64; k0 += 4) {
                ulonglong2 xa[8];
                #pragma unroll
                for (int a = 0; a < 8; a++)
                    xa[a] = *(const ulonglong2*)(xs + a * 68 + k0);
                #pragma unroll
                for (int jj = 0; jj < 4; jj++) {
                    const float* wr = sm + O_W1J + (lane + 32 * jj) * 66 + k0;
                    u64 w0 = *(const u64*)(wr);
                    u64 w1 = *(const u64*)(wr + 2);
                    #pragma unroll
                    for (int a = 0; a < 8; a++) {
                        fma2(acc[jj][a], w0, xa[a].x);
                        fma2(acc[jj][a], w1, xa[a].y);
                    }
                }
            }
            #pragma unroll
            for (int jj = 0; jj < 4; jj++) {
                float bj = sm[O_B1 + lane + 32 * jj];
                #pragma unroll
                for (int a = 0; a < 8; a++) {
                    float2 p = unpk(acc[jj][a]);
                    h1[a * 132 + lane + 32 * jj] = tanhf(p.x + p.y + bj);
                }
            }
        }
        __syncwarp();

        // ===== L2: h2 = tanh(h1 @ W2 + b2); energy; d2 -> xs =====
        {
            u64 acc[2][8];
            #pragma unroll
            for (int jj = 0; jj < 2; jj++)
                #pragma unroll
                for (int a = 0; a < 8; a++) acc[jj][a] = 0ull;

            for (int k0 = 0; k0 < 128; k0 += 4) {
                ulonglong2 xa[8];
                #pragma unroll
                for (int a = 0; a < 8; a++)
                    xa[a] = *(const ulonglong2*)(h1 + a * 132 + k0);
                #pragma unroll
                for (int jj = 0; jj < 2; jj++) {
                    const float* wr = sm + O_W2J + (lane + 32 * jj) * 130 + k0;
                    u64 w0 = *(const u64*)(wr);
                    u64 w1 = *(const u64*)(wr + 2);
                    #pragma unroll
                    for (int a = 0; a < 8; a++) {
                        fma2(acc[jj][a], w0, xa[a].x);
                        fma2(acc[jj][a], w1, xa[a].y);
                    }
                }
            }
            float bj0 = sm[O_B2 + lane],      bj1 = sm[O_B2 + lane + 32];
            float w30 = sm[O_W3 + lane],      w31 = sm[O_W3 + lane + 32];
            float myE = 0.f;
            #pragma unroll
            for (int a = 0; a < 8; a++) {
                float2 p0 = unpk(acc[0][a]);
                float2 p1 = unpk(acc[1][a]);
                float h20 = tanhf(p0.x + p0.y + bj0);
                float h21 = tanhf(p1.x + p1.y + bj1);
                float e = h20 * w30 + h21 * w31;
                xs[a * 68 + lane]      = w30 * (1.f - h20 * h20);
                xs[a * 68 + lane + 32] = w31 * (1.f - h21 * h21);
                #pragma unroll
                for (int off = 16; off; off >>= 1)
                    e += __shfl_xor_sync(0xffffffffu, e, off);
                if (lane == a) myE = e;     // lane a carries atom a's energy
            }
            if (lane < 8 && base + lane < natoms)
                atomicAdd(&energy[indices[base + lane]], myE + b3v);
        }
        __syncwarp();

        // ===== bwd1: g1 = (1 - h1^2) * (d2 @ W2^T), in place over h1 =====
        {
            u64 acc[4][8];
            #pragma unroll
            for (int jj = 0; jj < 4; jj++)
                #pragma unroll
                for (int a = 0; a < 8; a++) acc[jj][a] = 0ull;

            for (int k0 = 0; k0 < 64; k0 += 4) {
                ulonglong2 xa[8];
                #pragma unroll
                for (int a = 0; a < 8; a++)
                    xa[a] = *(const ulonglong2*)(xs + a * 68 + k0);
                #pragma unroll
                for (int jj = 0; jj < 4; jj++) {
                    const float* wr = sm + O_W2F + (lane + 32 * jj) * 66 + k0;
                    u64 w0 = *(const u64*)(wr);
                    u64 w1 = *(const u64*)(wr + 2);
                    #pragma unroll
                    for (int a = 0; a < 8; a++) {
                        fma2(acc[jj][a], w0, xa[a].x);
                        fma2(acc[jj][a], w1, xa[a].y);
                    }
                }
            }
            __syncwarp();
            #pragma unroll
            for (int jj = 0; jj < 4; jj++) {
                #pragma unroll
                for (int a = 0; a < 8; a++) {
                    float2 p = unpk(acc[jj][a]);
                    float* hp = h1 + a * 132 + lane + 32 * jj;
                    float h = *hp;
                    *hp = (p.x + p.y) * (1.f - h * h);
                }
            }
        }
        __syncwarp();

        // ===== bwd2: dEdD = g1 @ W1^T -> global =====
        {
            u64 acc[2][8];
            #pragma unroll
            for (int jj = 0; jj < 2; jj++)
                #pragma unroll
                for (int a = 0; a < 8; a++) acc[jj][a] = 0ull;

            for (int k0 = 0; k0 < 128; k0 += 4) {
                ulonglong2 xa[8];
                #pragma unroll
                for (int a = 0; a < 8; a++)
                    xa[a] = *(const ulonglong2*)(h1 + a * 132 + k0);
                #pragma unroll
                for (int jj = 0; jj < 2; jj++) {
                    const float* wr = sm + O_W1F + (lane + 32 * jj) * 130 + k0;
                    u64 w0 = *(const u64*)(wr);
                    u64 w1 = *(const u64*)(wr + 2);
                    #pragma unroll
                    for (int a = 0; a < 8; a++) {
                        fma2(acc[jj][a], w0, xa[a].x);
                        fma2(acc[jj][a], w1, xa[a].y);
                    }
                }
            }
            #pragma unroll
            for (int a = 0; a < 8; a++) {
                if (base + a < natoms) {
                    float2 p0 = unpk(acc[0][a]);
                    float2 p1 = unpk(acc[1][a]);
                    float* dst = g_dEdD + (size_t)(base + a) * 64;
                    dst[lane]      = p0.x + p0.y;
                    dst[lane + 32] = p1.x + p1.y;
                }
            }
        }
        __syncwarp();
    }
}

// ---------------------------------------------------------------------------
// Forces: 2 pairs per warp, 16-lane groups, float4 + __ldcs (80.7% DRAM).
// ---------------------------------------------------------------------------
__global__ void __launch_bounds__(256)
forces_kernel(const float* __restrict__ xd, const int* __restrict__ xd_indx,
              const int* __restrict__ uj, float* __restrict__ forces, int npairs)
{
    int w    = (blockIdx.x * blockDim.x + threadIdx.x) >> 5;
    int lane = threadIdx.x & 31;
    int li   = lane & 15;
    int pr   = lane >> 4;
    int p    = 2 * w + pr;
    if (2 * w >= npairs) return;
    bool valid = (p < npairs);
    int pc = valid ? p : (npairs - 1);

    int neigh = __ldg(xd_indx + 6 * pc);
    float4 gv = *(const float4*)(g_dEdD + (size_t)neigh * 64 + li * 4);

    const float4* xr = (const float4*)(xd + (size_t)pc * 192);
    float4 a0 = __ldcs(xr + li);
    float4 a1 = __ldcs(xr + 16 + li);
    float4 a2 = __ldcs(xr + 32 + li);

    float s0 = a0.x * gv.x + a0.y * gv.y + a0.z * gv.z + a0.w * gv.w;
    float s1 = a1.x * gv.x + a1.y * gv.y + a1.z * gv.z + a1.w * gv.w;
    float s2 = a2.x * gv.x + a2.y * gv.y + a2.z * gv.z + a2.w * gv.w;

    #pragma unroll
    for (int off = 8; off; off >>= 1) {
        s0 += __shfl_xor_sync(0xffffffffu, s0, off);
        s1 += __shfl_xor_sync(0xffffffffu, s1, off);
        s2 += __shfl_xor_sync(0xffffffffu, s2, off);
    }
    if (li == 0 && valid) {
        int j0 = __ldg(uj + 3 * pc);
        int j1 = __ldg(uj + 3 * pc + 1);
        int j2 = __ldg(uj + 3 * pc + 2);
        atomicAdd(&forces[3 * j0 + 0], -s0);
        atomicAdd(&forces[3 * j1 + 1], -s1);
        atomicAdd(&forces[3 * j2 + 2], -s2);
    }
}

// ---------------------------------------------------------------------------
extern "C" void kernel_launch(void* const* d_in, const int* in_sizes, int n_in,
                              void* d_out, int out_size)
{
    const float* x       = (const float*)d_in[0];
    const float* xd      = (const float*)d_in[1];
    const int*   indices = (const int*)  d_in[2];
    const int*   xd_indx = (const int*)  d_in[4];
    const int*   uj      = (const int*)  d_in[5];
    const float* W1      = (const float*)d_in[6];
    const float* b1      = (const float*)d_in[7];
    const float* W2      = (const float*)d_in[8];
    const float* b2      = (const float*)d_in[9];
    const float* W3      = (const float*)d_in[10];
    const float* b3      = (const float*)d_in[11];
    float* out = (float*)d_out;

    int natoms  = in_sizes[0] / 64;    // 50000
    int nstruct = in_sizes[3];         // 250
    int npairs  = in_sizes[5] / 3;     // 1000000

    cudaMemsetAsync(out, 0, (size_t)out_size * sizeof(float), 0);

    const int smem_bytes = SMEM_FLOATS * (int)sizeof(float);   // ~186 KB
    cudaFuncSetAttribute(mlp_kernel, cudaFuncAttributeMaxDynamicSharedMemorySize,
                         smem_bytes);
    mlp_kernel<<<148, 256, smem_bytes>>>(x, indices, W1, b1, W2, b2, W3, b3,
                                         out, natoms);

    int nwarps = (npairs + 1) / 2;
    int blocks = (nwarps + 7) / 8;
    forces_kernel<<<blocks, 256>>>(xd, xd_indx, uj, out + nstruct, npairs);
}

// round 7
// speedup vs baseline: 2.2537x; 1.0446x over previous
#include <cuda_runtime.h>
#include <math.h>
#include <stdint.h>

#define MAX_ATOMS 50000

__device__ float g_dEdD[MAX_ATOMS * 64];

// ---- smem float-offset map ----
// W1s: [d=64][t=128] as float2{hi,lo}, row stride 130 float2
// W2s: [t=128][j=64] as float2{hi,lo}, row stride 66 float2
#define O_W1S 0
#define O_W2S 16640              // 64*130*2 floats
#define O_B1  (O_W2S + 16896)    // 128*66*2 floats
#define O_B2  (O_B1 + 128)
#define O_W3  (O_B2 + 64)
#define O_H1  (O_W3 + 64)        // per-warp h1/g1 buffers [16][132]
#define H1W_FLOATS (16 * 132)
#define SMEM_FLOATS (O_H1 + 8 * H1W_FLOATS)   // 50688 floats = 202752 B

// m16n8k8 tf32 mma, fp32 accumulate, D==C in place
__device__ __forceinline__ void mma8(float* d,
                                     uint32_t a0, uint32_t a1, uint32_t a2, uint32_t a3,
                                     uint32_t b0, uint32_t b1) {
    asm("mma.sync.aligned.m16n8k8.row.col.f32.tf32.tf32.f32 "
        "{%0,%1,%2,%3}, {%4,%5,%6,%7}, {%8,%9}, {%0,%1,%2,%3};"
        : "+f"(d[0]), "+f"(d[1]), "+f"(d[2]), "+f"(d[3])
        : "r"(a0), "r"(a1), "r"(a2), "r"(a3), "r"(b0), "r"(b1));
}
// error-compensated tf32 split: v = hi + lo (+ O(2^-22))
__device__ __forceinline__ void split_tf32(float v, uint32_t& hi, uint32_t& lo) {
    uint32_t h;
    asm("cvt.rna.tf32.f32 %0, %1;" : "=r"(h) : "f"(v));
    float r = v - __uint_as_float(h);
    asm("cvt.rna.tf32.f32 %0, %1;" : "=r"(lo) : "f"(r));
    hi = h;
}

// ---------------------------------------------------------------------------
// MLP fwd+bwd on tensor cores. 256 thr = 8 autonomous warps; 16 atoms/warp
// per chunk, grid-stride. Four GEMMs per chunk via m16n8k8 tf32 with
// hi/lo error compensation (3 mma per k-tile).
// ---------------------------------------------------------------------------
__global__ void __launch_bounds__(256, 1)
mlp_kernel(const float* __restrict__ x, const int* __restrict__ indices,
           const float* __restrict__ W1, const float* __restrict__ b1,
           const float* __restrict__ W2, const float* __restrict__ b2,
           const float* __restrict__ W3, const float* __restrict__ b3,
           float* __restrict__ energy, int natoms)
{
    extern __shared__ float sm[];
    float2* W1s = (float2*)(sm + O_W1S);
    float2* W2s = (float2*)(sm + O_W2S);
    const int tid  = threadIdx.x;
    const int wid  = tid >> 5;
    const int lane = tid & 31;

    // ---- stage weights as {tf32-hi, tf32-lo} float2 ----
    for (int i = tid; i < 64 * 128; i += 256) {       // W1 [d][t]
        int d = i >> 7, t = i & 127;
        uint32_t hi, lo; split_tf32(W1[i], hi, lo);
        W1s[d * 130 + t] = make_float2(__uint_as_float(hi), __uint_as_float(lo));
    }
    for (int i = tid; i < 128 * 64; i += 256) {       // W2 [t][j]
        int t = i >> 6, j = i & 63;
        uint32_t hi, lo; split_tf32(W2[i], hi, lo);
        W2s[t * 66 + j] = make_float2(__uint_as_float(hi), __uint_as_float(lo));
    }
    if (tid < 128) sm[O_B1 + tid] = b1[tid];
    if (tid < 64)  { sm[O_B2 + tid] = b2[tid]; sm[O_W3 + tid] = W3[tid]; }
    const float b3v = b3[0];
    __syncthreads();

    float* h1s = sm + O_H1 + wid * H1W_FLOATS;    // [16][132], h1 then g1
    const int g = lane >> 2;     // groupID 0..7
    const int t = lane & 3;      // threadID in group
    const bool odd = t & 1;

    const int gwarp  = blockIdx.x * 8 + wid;
    const int nwarps = gridDim.x * 8;
    const int nchunk = (natoms + 15) >> 4;

    for (int chunk = gwarp; chunk < nchunk; chunk += nwarps) {
        const int base = chunk << 4;
        const int r0 = base + g, r1 = base + g + 8;
        const bool ok0 = r0 < natoms, ok1 = r1 < natoms;

        // ================= GEMM1: H1pre = X @ W1 (N=128, K=64) ============
        float acc[16][4];
        #pragma unroll
        for (int nt = 0; nt < 16; nt++)
            #pragma unroll
            for (int q = 0; q < 4; q++) acc[nt][q] = 0.f;

        #pragma unroll 1
        for (int s = 0; s < 8; s++) {
            int c = 8 * s + t;
            float ar0 = ok0 ? __ldg(x + (size_t)r0 * 64 + c)     : 0.f;
            float ar1 = ok1 ? __ldg(x + (size_t)r1 * 64 + c)     : 0.f;
            float ar2 = ok0 ? __ldg(x + (size_t)r0 * 64 + c + 4) : 0.f;
            float ar3 = ok1 ? __ldg(x + (size_t)r1 * 64 + c + 4) : 0.f;
            uint32_t ah0, al0, ah1, al1, ah2, al2, ah3, al3;
            split_tf32(ar0, ah0, al0); split_tf32(ar1, ah1, al1);
            split_tf32(ar2, ah2, al2); split_tf32(ar3, ah3, al3);
            const float2* wr0 = W1s + (8 * s + t) * 130;
            const float2* wr1 = W1s + (8 * s + t + 4) * 130;
            #pragma unroll
            for (int nt = 0; nt < 16; nt++) {
                float2 w0 = wr0[8 * nt + g];
                float2 w1 = wr1[8 * nt + g];
                uint32_t b0h = __float_as_uint(w0.x), b1h = __float_as_uint(w1.x);
                uint32_t b0l = __float_as_uint(w0.y), b1l = __float_as_uint(w1.y);
                mma8(acc[nt], ah0, ah1, ah2, ah3, b0h, b1h);
                mma8(acc[nt], al0, al1, al2, al3, b0h, b1h);
                mma8(acc[nt], ah0, ah1, ah2, ah3, b0l, b1l);
            }
        }
        // epi1: h1 = tanh(. + b1) -> h1s
        #pragma unroll
        for (int nt = 0; nt < 16; nt++) {
            int c = 8 * nt + 2 * t;
            float2 bb = *(const float2*)(sm + O_B1 + c);
            float2 v0 = make_float2(tanhf(acc[nt][0] + bb.x), tanhf(acc[nt][1] + bb.y));
            float2 v1 = make_float2(tanhf(acc[nt][2] + bb.x), tanhf(acc[nt][3] + bb.y));
            *(float2*)(h1s + g * 132 + c)       = v0;
            *(float2*)(h1s + (g + 8) * 132 + c) = v1;
        }
        __syncwarp();

        // ================= GEMM2: H2pre = H1 @ W2 (N=64, K=128) ===========
        float ac2[8][4];
        #pragma unroll
        for (int nt = 0; nt < 8; nt++)
            #pragma unroll
            for (int q = 0; q < 4; q++) ac2[nt][q] = 0.f;

        #pragma unroll 1
        for (int s = 0; s < 16; s++) {
            int c = 8 * s + t;
            float ar0 = h1s[g * 132 + c];
            float ar1 = h1s[(g + 8) * 132 + c];
            float ar2 = h1s[g * 132 + c + 4];
            float ar3 = h1s[(g + 8) * 132 + c + 4];
            uint32_t ah0, al0, ah1, al1, ah2, al2, ah3, al3;
            split_tf32(ar0, ah0, al0); split_tf32(ar1, ah1, al1);
            split_tf32(ar2, ah2, al2); split_tf32(ar3, ah3, al3);
            const float2* wr0 = W2s + (8 * s + t) * 66;
            const float2* wr1 = W2s + (8 * s + t + 4) * 66;
            #pragma unroll
            for (int nt = 0; nt < 8; nt++) {
                float2 w0 = wr0[8 * nt + g];
                float2 w1 = wr1[8 * nt + g];
                uint32_t b0h = __float_as_uint(w0.x), b1h = __float_as_uint(w1.x);
                uint32_t b0l = __float_as_uint(w0.y), b1l = __float_as_uint(w1.y);
                mma8(ac2[nt], ah0, ah1, ah2, ah3, b0h, b1h);
                mma8(ac2[nt], al0, al1, al2, al3, b0h, b1h);
                mma8(ac2[nt], ah0, ah1, ah2, ah3, b0l, b1l);
            }
        }
        // epi2: h2 = tanh(.+b2); energy; d2 = w3*(1-h2^2) kept in regs
        float d2v[8][4];
        float e0 = 0.f, e1 = 0.f;
        #pragma unroll
        for (int nt = 0; nt < 8; nt++) {
            int c = 8 * nt + 2 * t;
            float2 bb = *(const float2*)(sm + O_B2 + c);
            float2 w3 = *(const float2*)(sm + O_W3 + c);
            float h0 = tanhf(ac2[nt][0] + bb.x);
            float h1v = tanhf(ac2[nt][1] + bb.y);
            float h2v = tanhf(ac2[nt][2] + bb.x);
            float h3v = tanhf(ac2[nt][3] + bb.y);
            e0 += h0 * w3.x + h1v * w3.y;
            e1 += h2v * w3.x + h3v * w3.y;
            d2v[nt][0] = w3.x * (1.f - h0 * h0);
            d2v[nt][1] = w3.y * (1.f - h1v * h1v);
            d2v[nt][2] = w3.x * (1.f - h2v * h2v);
            d2v[nt][3] = w3.y * (1.f - h3v * h3v);
        }
        e0 += __shfl_xor_sync(0xffffffffu, e0, 1);
        e0 += __shfl_xor_sync(0xffffffffu, e0, 2);
        e1 += __shfl_xor_sync(0xffffffffu, e1, 1);
        e1 += __shfl_xor_sync(0xffffffffu, e1, 2);
        if (t == 0) {
            if (ok0) atomicAdd(&energy[__ldg(indices + r0)], e0 + b3v);
            if (ok1) atomicAdd(&energy[__ldg(indices + r1)], e1 + b3v);
        }

        // ============ GEMM3: G1pre = D2 @ W2^T (N=128, K=64) ==============
        // A-frags built from d2v D-frags via shuffles (no smem round-trip).
        float ac3[16][4];
        #pragma unroll
        for (int nt = 0; nt < 16; nt++)
            #pragma unroll
            for (int q = 0; q < 4; q++) ac3[nt][q] = 0.f;

        #pragma unroll 1
        for (int s = 0; s < 8; s++) {
            int srcA = 4 * g + (t >> 1);
            int srcB = srcA + 2;
            float q0 = __shfl_sync(0xffffffffu, d2v[s][0], srcA);
            float q1 = __shfl_sync(0xffffffffu, d2v[s][1], srcA);
            float q2 = __shfl_sync(0xffffffffu, d2v[s][2], srcA);
            float q3 = __shfl_sync(0xffffffffu, d2v[s][3], srcA);
            float p0 = __shfl_sync(0xffffffffu, d2v[s][0], srcB);
            float p1 = __shfl_sync(0xffffffffu, d2v[s][1], srcB);
            float p2 = __shfl_sync(0xffffffffu, d2v[s][2], srcB);
            float p3 = __shfl_sync(0xffffffffu, d2v[s][3], srcB);
            float ar0 = odd ? q1 : q0;     // (g,     8s+t)
            float ar1 = odd ? q3 : q2;     // (g+8,   8s+t)
            float ar2 = odd ? p1 : p0;     // (g,     8s+t+4)
            float ar3 = odd ? p3 : p2;     // (g+8,   8s+t+4)
            uint32_t ah0, al0, ah1, al1, ah2, al2, ah3, al3;
            split_tf32(ar0, ah0, al0); split_tf32(ar1, ah1, al1);
            split_tf32(ar2, ah2, al2); split_tf32(ar3, ah3, al3);
            #pragma unroll
            for (int nt = 0; nt < 16; nt++) {
                float2 w0 = W2s[(8 * nt + g) * 66 + 8 * s + t];
                float2 w1 = W2s[(8 * nt + g) * 66 + 8 * s + t + 4];
                uint32_t b0h = __float_as_uint(w0.x), b1h = __float_as_uint(w1.x);
                uint32_t b0l = __float_as_uint(w0.y), b1l = __float_as_uint(w1.y);
                mma8(ac3[nt], ah0, ah1, ah2, ah3, b0h, b1h);
                mma8(ac3[nt], al0, al1, al2, al3, b0h, b1h);
                mma8(ac3[nt], ah0, ah1, ah2, ah3, b0l, b1l);
            }
        }
        // epi3: g1 = G1pre * (1 - h1^2), in place over h1s
        #pragma unroll
        for (int nt = 0; nt < 16; nt++) {
            int c = 8 * nt + 2 * t;
            float2* ptr0 = (float2*)(h1s + g * 132 + c);
            float2* ptr1 = (float2*)(h1s + (g + 8) * 132 + c);
            float2 h0 = *ptr0, h1v = *ptr1;
            *ptr0 = make_float2(ac3[nt][0] * (1.f - h0.x * h0.x),
                                ac3[nt][1] * (1.f - h0.y * h0.y));
            *ptr1 = make_float2(ac3[nt][2] * (1.f - h1v.x * h1v.x),
                                ac3[nt][3] * (1.f - h1v.y * h1v.y));
        }
        __syncwarp();

        // ============ GEMM4: dEdD = G1 @ W1^T (N=64, K=128) ===============
        float ac4[8][4];
        #pragma unroll
        for (int nt = 0; nt < 8; nt++)
            #pragma unroll
            for (int q = 0; q < 4; q++) ac4[nt][q] = 0.f;

        #pragma unroll 1
        for (int s = 0; s < 16; s++) {
            int c = 8 * s + t;
            float ar0 = h1s[g * 132 + c];
            float ar1 = h1s[(g + 8) * 132 + c];
            float ar2 = h1s[g * 132 + c + 4];
            float ar3 = h1s[(g + 8) * 132 + c + 4];
            uint32_t ah0, al0, ah1, al1, ah2, al2, ah3, al3;
            split_tf32(ar0, ah0, al0); split_tf32(ar1, ah1, al1);
            split_tf32(ar2, ah2, al2); split_tf32(ar3, ah3, al3);
            #pragma unroll
            for (int nt = 0; nt < 8; nt++) {
                float2 w0 = W1s[(8 * nt + g) * 130 + 8 * s + t];
                float2 w1 = W1s[(8 * nt + g) * 130 + 8 * s + t + 4];
                uint32_t b0h = __float_as_uint(w0.x), b1h = __float_as_uint(w1.x);
                uint32_t b0l = __float_as_uint(w0.y), b1l = __float_as_uint(w1.y);
                mma8(ac4[nt], ah0, ah1, ah2, ah3, b0h, b1h);
                mma8(ac4[nt], al0, al1, al2, al3, b0h, b1h);
                mma8(ac4[nt], ah0, ah1, ah2, ah3, b0l, b1l);
            }
        }
        // epi4: store dEdD
        #pragma unroll
        for (int nt = 0; nt < 8; nt++) {
            int c = 8 * nt + 2 * t;
            if (ok0)
                *(float2*)(g_dEdD + (size_t)r0 * 64 + c)
                    = make_float2(ac4[nt][0], ac4[nt][1]);
            if (ok1)
                *(float2*)(g_dEdD + (size_t)r1 * 64 + c)
                    = make_float2(ac4[nt][2], ac4[nt][3]);
        }
        __syncwarp();
    }
}

// ---------------------------------------------------------------------------
// Forces: 4 pairs per warp, 8-lane groups, 8 LDG.128 in flight per lane.
// ---------------------------------------------------------------------------
__global__ void __launch_bounds__(256)
forces_kernel(const float* __restrict__ xd, const int* __restrict__ xd_indx,
              const int* __restrict__ uj, float* __restrict__ forces, int npairs)
{
    int w    = (blockIdx.x * blockDim.x + threadIdx.x) >> 5;
    int lane = threadIdx.x & 31;
    int li   = lane & 7;
    int pr   = lane >> 3;
    int p    = 4 * w + pr;
    if (4 * w >= npairs) return;
    bool valid = (p < npairs);
    int pc = valid ? p : (npairs - 1);

    int neigh = __ldg(xd_indx + 6 * pc);
    const float4* gp = (const float4*)(g_dEdD + (size_t)neigh * 64);
    float4 ga = gp[2 * li], gb = gp[2 * li + 1];

    const float4* xr = (const float4*)(xd + (size_t)pc * 192);
    float4 a0 = __ldcs(xr + 2 * li),      b0 = __ldcs(xr + 2 * li + 1);
    float4 a1 = __ldcs(xr + 16 + 2 * li), b1 = __ldcs(xr + 17 + 2 * li);
    float4 a2 = __ldcs(xr + 32 + 2 * li), b2 = __ldcs(xr + 33 + 2 * li);

    float s0 = a0.x*ga.x + a0.y*ga.y + a0.z*ga.z + a0.w*ga.w
             + b0.x*gb.x + b0.y*gb.y + b0.z*gb.z + b0.w*gb.w;
    float s1 = a1.x*ga.x + a1.y*ga.y + a1.z*ga.z + a1.w*ga.w
             + b1.x*gb.x + b1.y*gb.y + b1.z*gb.z + b1.w*gb.w;
    float s2 = a2.x*ga.x + a2.y*ga.y + a2.z*ga.z + a2.w*ga.w
             + b2.x*gb.x + b2.y*gb.y + b2.z*gb.z + b2.w*gb.w;

    #pragma unroll
    for (int off = 4; off; off >>= 1) {
        s0 += __shfl_xor_sync(0xffffffffu, s0, off);
        s1 += __shfl_xor_sync(0xffffffffu, s1, off);
        s2 += __shfl_xor_sync(0xffffffffu, s2, off);
    }
    if (li == 0 && valid) {
        int j0 = __ldg(uj + 3 * pc);
        int j1 = __ldg(uj + 3 * pc + 1);
        int j2 = __ldg(uj + 3 * pc + 2);
        atomicAdd(&forces[3 * j0 + 0], -s0);
        atomicAdd(&forces[3 * j1 + 1], -s1);
        atomicAdd(&forces[3 * j2 + 2], -s2);
    }
}

// ---------------------------------------------------------------------------
extern "C" void kernel_launch(void* const* d_in, const int* in_sizes, int n_in,
                              void* d_out, int out_size)
{
    const float* x       = (const float*)d_in[0];
    const float* xd      = (const float*)d_in[1];
    const int*   indices = (const int*)  d_in[2];
    const int*   xd_indx = (const int*)  d_in[4];
    const int*   uj      = (const int*)  d_in[5];
    const float* W1      = (const float*)d_in[6];
    const float* b1      = (const float*)d_in[7];
    const float* W2      = (const float*)d_in[8];
    const float* b2      = (const float*)d_in[9];
    const float* W3      = (const float*)d_in[10];
    const float* b3      = (const float*)d_in[11];
    float* out = (float*)d_out;

    int natoms  = in_sizes[0] / 64;    // 50000
    int nstruct = in_sizes[3];         // 250
    int npairs  = in_sizes[5] / 3;     // 1000000

    cudaMemsetAsync(out, 0, (size_t)out_size * sizeof(float), 0);

    const int smem_bytes = SMEM_FLOATS * (int)sizeof(float);   // 202,752 B
    cudaFuncSetAttribute(mlp_kernel, cudaFuncAttributeMaxDynamicSharedMemorySize,
                         smem_bytes);
    mlp_kernel<<<148, 256, smem_bytes>>>(x, indices, W1, b1, W2, b2, W3, b3,
                                         out, natoms);

    int nwarps = (npairs + 3) / 4;
    int blocks = (nwarps + 7) / 8;
    forces_kernel<<<blocks, 256>>>(xd, xd_indx, uj, out + nstruct, npairs);
}